// round 13
// baseline (speedup 1.0000x reference)
#include <cuda_runtime.h>
#include <cstdint>

#define NPTS 500000
#define NSEG 80000
#define SEGW 92
#define DIN 182
#define NT_B 3907
#define NT_A 625
#define GRID 296
#define GRID2 148
#define KP 92

__device__ __align__(16) float g_seg[NSEG * SEGW];
__device__ __align__(16) float g_Y[(size_t)NSEG * 128];
__device__ float g_sum[128], g_sumsq[128], g_scale[128], g_shift[128];
__device__ int g_flags;
__device__ int g_cnt[NSEG];
__device__ int g_base[NSEG];
__device__ int g_cur[NSEG];
__device__ int g_pidx[NPTS];
__device__ int g_blksum[640];
__device__ int g_blkoff[640];

// ---- f32x2 packed helpers ----
__device__ __forceinline__ unsigned long long pk2(float a) {
    unsigned long long r; asm("mov.b64 %0,{%1,%1};" : "=l"(r) : "f"(a)); return r;
}
__device__ __forceinline__ void upk(unsigned long long v, float& a, float& b) {
    asm("mov.b64 {%0,%1},%2;" : "=f"(a), "=f"(b) : "l"(v));
}
__device__ __forceinline__ void fma2(unsigned long long& d, unsigned long long a, unsigned long long b) {
    asm("fma.rn.f32x2 %0,%1,%2,%0;" : "+l"(d) : "l"(a), "l"(b));
}
__device__ __forceinline__ int fg_of(const void* m, int p, int fl) {
    if (fl & 2) return ((const float*)m)[p] != 0.0f;
    if (fl & 1) return ((const unsigned char*)m)[p] != 0;
    return ((const int*)m)[p] != 0;
}

// ---------------- K0: zero small scratch ----------------
__global__ __launch_bounds__(256) void k_zero() {
    int i = blockIdx.x * blockDim.x + threadIdx.x;
    int st = gridDim.x * blockDim.x;
    for (int j = i; j < NSEG; j += st) g_cnt[j] = 0;
    if (i < 128) { g_sum[i] = 0.f; g_sumsq[i] = 0.f; }
    if (i == 0) g_flags = 0;
}

// ---------------- K1: detect fg_mask dtype ----------------
__global__ __launch_bounds__(256) void k_detect(const unsigned int* __restrict__ w) {
    int f = 0;
    for (int i = blockIdx.x * blockDim.x + threadIdx.x; i < 125000; i += gridDim.x * blockDim.x) {
        unsigned int x = w[i];
        if (x == 0x3f800000u) f |= 2;
        else if (x > 1u) f |= 1;
    }
    if (f) atomicOr(&g_flags, f);
}

// ---------------- K2a: histogram ----------------
__global__ __launch_bounds__(256) void k_hist(const int* __restrict__ cidx,
                                              const void* __restrict__ fgm) {
    const int fl = g_flags;
    for (int p = blockIdx.x * blockDim.x + threadIdx.x; p < NPTS; p += gridDim.x * blockDim.x)
        atomicAdd(&g_cnt[cidx[p] * 2 + fg_of(fgm, p, fl)], 1);
}

// ---------------- K2b: three-phase exclusive scan ----------------
__global__ __launch_bounds__(128) void k_scan1() {
    __shared__ int sh[128];
    const int t = threadIdx.x;
    const int i = blockIdx.x * 128 + t;
    int c = g_cnt[i];
    sh[t] = c;
    __syncthreads();
    int acc = c;
    #pragma unroll
    for (int off = 1; off < 128; off <<= 1) {
        int u = (t >= off) ? sh[t - off] : 0;
        __syncthreads();
        acc += u;
        sh[t] = acc;
        __syncthreads();
    }
    g_base[i] = acc - c;
    if (t == 127) g_blksum[blockIdx.x] = acc;
}
__global__ __launch_bounds__(1024) void k_scan2() {
    __shared__ int sh[1024];
    const int t = threadIdx.x;
    int c = (t < NT_A) ? g_blksum[t] : 0;
    sh[t] = c;
    __syncthreads();
    int acc = c;
    #pragma unroll
    for (int off = 1; off < 1024; off <<= 1) {
        int u = (t >= off) ? sh[t - off] : 0;
        __syncthreads();
        acc += u;
        sh[t] = acc;
        __syncthreads();
    }
    if (t < NT_A) g_blkoff[t] = acc - c;
}
__global__ __launch_bounds__(128) void k_scan3() {
    const int i = blockIdx.x * 128 + threadIdx.x;
    int v = g_base[i] + g_blkoff[blockIdx.x];
    g_base[i] = v;
    g_cur[i] = v;
}

// ---------------- K2c: reorder ----------------
__global__ __launch_bounds__(256) void k_reorder(const int* __restrict__ cidx,
                                                 const void* __restrict__ fgm) {
    const int fl = g_flags;
    for (int p = blockIdx.x * blockDim.x + threadIdx.x; p < NPTS; p += gridDim.x * blockDim.x) {
        int s = cidx[p] * 2 + fg_of(fgm, p, fl);
        int pos = atomicAdd(&g_cur[s], 1);
        g_pidx[pos] = p;
    }
}

// ---------------- K2d: gather-sum per segment ----------------
__device__ __forceinline__ float4 ldpt(const float* pts, const float* proj,
                                       const float* feat, const float* logi,
                                       int p, int lane) {
    if (lane < 16)  return *(const float4*)(feat + (size_t)p * 64 + lane * 4);
    if (lane < 21)  return *(const float4*)(logi + (size_t)p * 20 + (lane - 16) * 4);
    if (lane == 21) return *(const float4*)(pts + (size_t)p * 4);
    const float* pr = proj + (size_t)p * 3;
    return make_float4(pr[0], pr[1], pr[2], 0.f);
}

__global__ __launch_bounds__(256) void k_segsum(const float* __restrict__ pts,
                                                const float* __restrict__ proj,
                                                const float* __restrict__ feat,
                                                const float* __restrict__ logi) {
    const int lane = threadIdx.x & 31;
    const int gw = (blockIdx.x * blockDim.x + threadIdx.x) >> 5;
    const int nw = (gridDim.x * blockDim.x) >> 5;
    for (int s = gw; s < NSEG; s += nw) {
        const int n = g_cnt[s];
        const int base = g_base[s];
        float4 acc = make_float4(0.f, 0.f, 0.f, 0.f);
        if (lane < 23) {
            int i = 0;
            for (; i + 2 <= n; i += 2) {
                int p0 = g_pidx[base + i];
                int p1 = g_pidx[base + i + 1];
                float4 v0 = ldpt(pts, proj, feat, logi, p0, lane);
                float4 v1 = ldpt(pts, proj, feat, logi, p1, lane);
                acc.x += v0.x + v1.x; acc.y += v0.y + v1.y;
                acc.z += v0.z + v1.z; acc.w += v0.w + v1.w;
            }
            if (i < n) {
                float4 v = ldpt(pts, proj, feat, logi, g_pidx[base + i], lane);
                acc.x += v.x; acc.y += v.y; acc.z += v.z; acc.w += v.w;
            }
            if (lane == 22) acc.w = (float)n;
            *(float4*)(g_seg + (size_t)s * SEGW + lane * 4) = acc;
        }
    }
}

// ======== FFMA2 inner block (segmm): 16m x 4n per thread ========
#define MMA_BODY(ws, xs, acc, tx, ty)                                        \
    _Pragma("unroll 4")                                                       \
    for (int k = 0; k < KP; k++) {                                            \
        const float* xr = (xs) + k * 128 + (ty) * 16;                         \
        ulonglong2 a0 = *(const ulonglong2*)xr;                               \
        ulonglong2 a1 = *(const ulonglong2*)(xr + 4);                         \
        ulonglong2 a2 = *(const ulonglong2*)(xr + 8);                         \
        ulonglong2 a3 = *(const ulonglong2*)(xr + 12);                        \
        float4 b = *(const float4*)((ws) + k * 128 + (tx) * 4);               \
        unsigned long long b0 = pk2(b.x), b1 = pk2(b.y),                      \
                           b2 = pk2(b.z), b3 = pk2(b.w);                      \
        fma2(acc[0], a0.x, b0);  fma2(acc[1], a0.y, b0);                      \
        fma2(acc[2], a1.x, b0);  fma2(acc[3], a1.y, b0);                      \
        fma2(acc[4], a2.x, b0);  fma2(acc[5], a2.y, b0);                      \
        fma2(acc[6], a3.x, b0);  fma2(acc[7], a3.y, b0);                      \
        fma2(acc[8], a0.x, b1);  fma2(acc[9], a0.y, b1);                      \
        fma2(acc[10], a1.x, b1); fma2(acc[11], a1.y, b1);                     \
        fma2(acc[12], a2.x, b1); fma2(acc[13], a2.y, b1);                     \
        fma2(acc[14], a3.x, b1); fma2(acc[15], a3.y, b1);                     \
        fma2(acc[16], a0.x, b2); fma2(acc[17], a0.y, b2);                     \
        fma2(acc[18], a1.x, b2); fma2(acc[19], a1.y, b2);                     \
        fma2(acc[20], a2.x, b2); fma2(acc[21], a2.y, b2);                     \
        fma2(acc[22], a3.x, b2); fma2(acc[23], a3.y, b2);                     \
        fma2(acc[24], a0.x, b3); fma2(acc[25], a0.y, b3);                     \
        fma2(acc[26], a1.x, b3); fma2(acc[27], a1.y, b3);                     \
        fma2(acc[28], a2.x, b3); fma2(acc[29], a2.y, b3);                     \
        fma2(acc[30], a3.x, b3); fma2(acc[31], a3.y, b3);                     \
    }

// ---------------- K3: pass A — Y[s] = W2*mean[s] + bias ----------------
#define SMEM_A ((KP * 128 * 2 + 128) * 4)
__global__ __launch_bounds__(256, 2) void k_segmm(const float* __restrict__ W,
                                                  const float* __restrict__ bias) {
    extern __shared__ __align__(16) float smf[];
    float* ws = smf;
    float* xs = smf + KP * 128;
    float* bias_s = smf + KP * 256;

    const int tid = threadIdx.x;
    const int tx = tid & 31, ty = tid >> 5;
    const int r = tid & 127, half = tid >> 7;

    for (int i = tid; i < KP * 128; i += 256) {
        int k = i >> 7, n = i & 127;
        ws[i] = (k < 91) ? W[n * DIN + 91 + k] : 0.f;
    }
    if (tid < 128) bias_s[tid] = bias[tid];
    __syncthreads();

    for (int t = blockIdx.x; t < NT_A; t += GRID) {
        const int s = t * 128 + r;
        const float* row = g_seg + (size_t)s * SEGW;
        float cnt = row[91];
        float inv = (cnt > 0.f) ? (1.0f / cnt) : 0.f;
        float* xc = xs + r;
        if (half == 0) {
            #pragma unroll
            for (int q = 0; q < 12; q++) {
                float4 f = *(const float4*)(row + 4 * q);
                xc[(4 * q + 0) * 128] = f.x * inv; xc[(4 * q + 1) * 128] = f.y * inv;
                xc[(4 * q + 2) * 128] = f.z * inv; xc[(4 * q + 3) * 128] = f.w * inv;
            }
        } else {
            #pragma unroll
            for (int q = 0; q < 10; q++) {
                float4 f = *(const float4*)(row + 48 + 4 * q);
                xc[(48 + 4 * q) * 128] = f.x * inv; xc[(49 + 4 * q) * 128] = f.y * inv;
                xc[(50 + 4 * q) * 128] = f.z * inv; xc[(51 + 4 * q) * 128] = f.w * inv;
            }
            xc[88 * 128] = row[88] * inv;
            xc[89 * 128] = row[89] * inv;
            xc[90 * 128] = row[90] * inv;
            xc[91 * 128] = 0.f;
        }
        __syncthreads();

        unsigned long long acc[32];
        #pragma unroll
        for (int i = 0; i < 32; i++) acc[i] = 0ull;
        MMA_BODY(ws, xs, acc, tx, ty)

        const float bj0 = bias_s[tx * 4], bj1 = bias_s[tx * 4 + 1];
        const float bj2 = bias_s[tx * 4 + 2], bj3 = bias_s[tx * 4 + 3];
        #pragma unroll
        for (int pr = 0; pr < 8; pr++) {
            int s0 = t * 128 + ty * 16 + 2 * pr;
            float c0[4], c1[4];
            upk(acc[pr],      c0[0], c1[0]);
            upk(acc[8 + pr],  c0[1], c1[1]);
            upk(acc[16 + pr], c0[2], c1[2]);
            upk(acc[24 + pr], c0[3], c1[3]);
            *(float4*)(g_Y + (size_t)s0 * 128 + tx * 4) =
                make_float4(c0[0] + bj0, c0[1] + bj1, c0[2] + bj2, c0[3] + bj3);
            *(float4*)(g_Y + (size_t)(s0 + 1) * 128 + tx * 4) =
                make_float4(c1[0] + bj0, c1[1] + bj1, c1[2] + bj2, c1[3] + bj3);
        }
        __syncthreads();
    }
}

// ---------------- K4: pass B — double-buffered 512-thread GEMM ----------------
// smem: ws 92x128 | xs0 | xs1 | red 256 | sidx 2x128  = 143360 B
#define SMEM_P ((KP * 128 * 3 + 256 + 256) * 4)

__device__ __forceinline__ float4 ldchunk(const float* pts, const float* proj,
                                          const float* feat, const float* logi,
                                          int p, int c) {
    if (c < 16)  return *(const float4*)(feat + (size_t)p * 64 + c * 4);
    if (c < 21)  return *(const float4*)(logi + (size_t)p * 20 + (c - 16) * 4);
    if (c == 21) return *(const float4*)(pts + (size_t)p * 4);
    const float* pr = proj + (size_t)p * 3;
    return make_float4(pr[0], pr[1], pr[2], 0.f);
}

// quarter-based gather: thread (r, q) fills chunks q*6 .. q*6+5 (q=3: 5 chunks)
__device__ __forceinline__ void gather_q(
    float* xs, int* sidx, int t,
    const float* pts, const float* proj, const float* feat, const float* logi,
    const int* cidx, const void* fgm, int fl, int r, int q) {
    const int p = t * 128 + r;
    const bool ok = p < NPTS;
    if (q == 3) sidx[r] = ok ? (cidx[p] * 2 + fg_of(fgm, p, fl)) : 0;
    #pragma unroll
    for (int j = 0; j < 6; j++) {
        int c = q * 6 + j;
        if (c <= 22) {
            float4 v = ok ? ldchunk(pts, proj, feat, logi, p, c)
                          : make_float4(0.f, 0.f, 0.f, 0.f);
            float* xc = xs + c * 4 * 128 + r;
            xc[0]       = v.x;
            xc[128]     = v.y;
            xc[256]     = v.z;
            xc[384]     = v.w;
        }
    }
}

__global__ __launch_bounds__(512, 1) void k_ptmm2(
    const float* __restrict__ pts, const float* __restrict__ proj,
    const float* __restrict__ feat, const float* __restrict__ logi,
    const int* __restrict__ cidx, const void* __restrict__ fgm,
    const float* __restrict__ W, float* __restrict__ hout)
{
    extern __shared__ __align__(16) float smf[];
    float* ws = smf;                        // 92*128
    float* xsb[2] = { smf + KP * 128, smf + KP * 256 };
    float* red = smf + KP * 384;            // 256
    int* sidxb[2] = { (int*)(smf + KP * 384 + 256), (int*)(smf + KP * 384 + 384) };

    const int tid = threadIdx.x;
    const int tx = tid & 31, ty = tid >> 5;    // compute: n 4-group, m 8-group
    const int r = tid & 127, q = tid >> 7;     // gather: row, chunk-quarter
    const int fl = g_flags;

    for (int i = tid; i < KP * 128; i += 512) {
        int k = i >> 7, n = i & 127;
        ws[i] = (k < 91) ? W[n * DIN + k] : 0.f;
    }
    float s_sum[4], s_sq[4];
    #pragma unroll
    for (int j = 0; j < 4; j++) { s_sum[j] = 0.f; s_sq[j] = 0.f; }

    int t = blockIdx.x;
    if (t < NT_B)
        gather_q(xsb[0], sidxb[0], t, pts, proj, feat, logi, cidx, fgm, fl, r, q);
    __syncthreads();

    int buf = 0;
    for (; t < NT_B; t += GRID2) {
        const float* xs = xsb[buf];
        const int* sidx = sidxb[buf];
        // prefetch next tile into back buffer (no sync needed: disjoint)
        if (t + GRID2 < NT_B)
            gather_q(xsb[buf ^ 1], sidxb[buf ^ 1], t + GRID2,
                     pts, proj, feat, logi, cidx, fgm, fl, r, q);

        unsigned long long acc[16];
        #pragma unroll
        for (int i = 0; i < 16; i++) acc[i] = 0ull;

        #pragma unroll 4
        for (int k = 0; k < KP; k++) {
            const float* xr = xs + k * 128 + ty * 8;
            ulonglong2 a0 = *(const ulonglong2*)xr;
            ulonglong2 a1 = *(const ulonglong2*)(xr + 4);
            float4 b = *(const float4*)(ws + k * 128 + tx * 4);
            unsigned long long b0 = pk2(b.x), b1 = pk2(b.y), b2 = pk2(b.z), b3 = pk2(b.w);
            fma2(acc[0],  a0.x, b0); fma2(acc[1],  a0.y, b0);
            fma2(acc[2],  a1.x, b0); fma2(acc[3],  a1.y, b0);
            fma2(acc[4],  a0.x, b1); fma2(acc[5],  a0.y, b1);
            fma2(acc[6],  a1.x, b1); fma2(acc[7],  a1.y, b1);
            fma2(acc[8],  a0.x, b2); fma2(acc[9],  a0.y, b2);
            fma2(acc[10], a1.x, b2); fma2(acc[11], a1.y, b2);
            fma2(acc[12], a0.x, b3); fma2(acc[13], a0.y, b3);
            fma2(acc[14], a1.x, b3); fma2(acc[15], a1.y, b3);
        }

        // epilogue: Y gather + bias-free add + stats + store
        #pragma unroll
        for (int i = 0; i < 4; i++) {
            int rl = ty * 8 + 2 * i;
            int row0 = t * 128 + rl;
            int s0 = sidx[rl], s1 = sidx[rl + 1];
            float4 y0 = *(const float4*)(g_Y + (size_t)s0 * 128 + tx * 4);
            float4 y1 = *(const float4*)(g_Y + (size_t)s1 * 128 + tx * 4);
            float c0[4], c1[4];
            upk(acc[i],      c0[0], c1[0]);
            upk(acc[4 + i],  c0[1], c1[1]);
            upk(acc[8 + i],  c0[2], c1[2]);
            upk(acc[12 + i], c0[3], c1[3]);
            c0[0] += y0.x; c0[1] += y0.y; c0[2] += y0.z; c0[3] += y0.w;
            c1[0] += y1.x; c1[1] += y1.y; c1[2] += y1.z; c1[3] += y1.w;
            if (row0 < NPTS) {
                #pragma unroll
                for (int j = 0; j < 4; j++) { s_sum[j] += c0[j]; s_sq[j] += c0[j] * c0[j]; }
                *(float4*)(hout + (size_t)row0 * 128 + tx * 4) =
                    make_float4(c0[0], c0[1], c0[2], c0[3]);
                if (row0 + 1 < NPTS) {
                    #pragma unroll
                    for (int j = 0; j < 4; j++) { s_sum[j] += c1[j]; s_sq[j] += c1[j] * c1[j]; }
                    *(float4*)(hout + (size_t)(row0 + 1) * 128 + tx * 4) =
                        make_float4(c1[0], c1[1], c1[2], c1[3]);
                }
            }
        }
        __syncthreads();
        buf ^= 1;
    }

    // per-CTA stats reduction
    if (tid < 256) red[tid] = 0.f;
    __syncthreads();
    #pragma unroll
    for (int j = 0; j < 4; j++) {
        atomicAdd(&red[tx * 4 + j], s_sum[j]);
        atomicAdd(&red[128 + tx * 4 + j], s_sq[j]);
    }
    __syncthreads();
    if (tid < 128) {
        atomicAdd(&g_sum[tid], red[tid]);
        atomicAdd(&g_sumsq[tid], red[128 + tid]);
    }
}

// ---------------- K5: BN coefficients ----------------
__global__ void k_bn(const float* __restrict__ gamma, const float* __restrict__ beta) {
    int c = threadIdx.x;
    float mu = g_sum[c] * (1.0f / NPTS);
    float var = g_sumsq[c] * (1.0f / NPTS) - mu * mu;
    float sc = gamma[c] * rsqrtf(var + 1e-5f);
    g_scale[c] = sc;
    g_shift[c] = beta[c] - mu * sc;
}

// ---------------- K6: normalize + LeakyReLU ----------------
__global__ __launch_bounds__(256) void k_apply(float* __restrict__ out) {
    int64_t i0 = (int64_t)blockIdx.x * blockDim.x + threadIdx.x;
    int64_t st = (int64_t)gridDim.x * blockDim.x;
    float4* o4 = (float4*)out;
    for (int64_t i = i0; i < (int64_t)NPTS * 32; i += st) {
        float4 v = o4[i];
        int c = (int)(i & 31) * 4;
        float a0 = v.x * g_scale[c]     + g_shift[c];
        float a1 = v.y * g_scale[c + 1] + g_shift[c + 1];
        float a2 = v.z * g_scale[c + 2] + g_shift[c + 2];
        float a3 = v.w * g_scale[c + 3] + g_shift[c + 3];
        v.x = a0 >= 0.f ? a0 : 0.1f * a0;
        v.y = a1 >= 0.f ? a1 : 0.1f * a1;
        v.z = a2 >= 0.f ? a2 : 0.1f * a2;
        v.w = a3 >= 0.f ? a3 : 0.1f * a3;
        o4[i] = v;
    }
}

extern "C" void kernel_launch(void* const* d_in, const int* in_sizes, int n_in,
                              void* d_out, int out_size) {
    const float* pts  = (const float*)d_in[0];
    const float* proj = (const float*)d_in[1];
    const float* feat = (const float*)d_in[2];
    const float* logi = (const float*)d_in[3];
    const int*   cidx = (const int*)d_in[4];
    const void*  fgm  = d_in[5];
    const float* W    = (const float*)d_in[6];
    const float* b    = (const float*)d_in[7];
    const float* gamma= (const float*)d_in[8];
    const float* beta = (const float*)d_in[9];
    float* out = (float*)d_out;

    cudaFuncSetAttribute(k_segmm, cudaFuncAttributeMaxDynamicSharedMemorySize, SMEM_A);
    cudaFuncSetAttribute(k_ptmm2, cudaFuncAttributeMaxDynamicSharedMemorySize, SMEM_P);

    k_zero<<<320, 256>>>();
    k_detect<<<64, 256>>>((const unsigned int*)fgm);
    k_hist<<<512, 256>>>(cidx, fgm);
    k_scan1<<<NT_A, 128>>>();
    k_scan2<<<1, 1024>>>();
    k_scan3<<<NT_A, 128>>>();
    k_reorder<<<512, 256>>>(cidx, fgm);
    k_segsum<<<2500, 256>>>(pts, proj, feat, logi);
    k_segmm<<<GRID, 256, SMEM_A>>>(W, b);
    k_ptmm2<<<GRID2, 512, SMEM_P>>>(pts, proj, feat, logi, cidx, fgm, W, out);
    k_bn<<<1, 128>>>(gamma, beta);
    k_apply<<<2048, 256>>>(out);
}